// round 1
// baseline (speedup 1.0000x reference)
#include <cuda_runtime.h>
#include <math.h>

#define NS 100000
#define H 128
#define NBLK 512
#define NTHREADS 256
#define WPB (NTHREADS / 32)
#define TOTW (NBLK * WPB)
#define SCR_W (2 * H + 2)

// Deterministic two-stage reduction scratch (no atomics to global).
__device__ float g_scratch[NBLK][SCR_W];

__device__ __forceinline__ void wreduce2(float& a, float& b) {
#pragma unroll
    for (int o = 16; o > 0; o >>= 1) {
        a += __shfl_xor_sync(0xffffffffu, a, o);
        b += __shfl_xor_sync(0xffffffffu, b, o);
    }
}

// Pass 1: single sweep over e. One warp per row (32 lanes x float4 = 128 floats).
// Per row: dot(q,e_n), ||e_n||^2 -> c_n = cos(q,e_n); accumulate
//   S+ = sum max(c,0), S- = sum max(-c,0),
//   P+[h] = sum max(c,0) e[n,h], P-[h] = sum max(-c,0) e[n,h].
__global__ __launch_bounds__(NTHREADS) void fp_pass1(const float* __restrict__ e,
                                                     const float* __restrict__ q) {
    const int lane = threadIdx.x & 31;
    const int warp = threadIdx.x >> 5;
    const int gw = blockIdx.x * WPB + warp;

    // q fragment + ||q||
    float4 qf = reinterpret_cast<const float4*>(q)[lane];
    float qn = qf.x * qf.x + qf.y * qf.y + qf.z * qf.z + qf.w * qf.w;
#pragma unroll
    for (int o = 16; o > 0; o >>= 1) qn += __shfl_xor_sync(0xffffffffu, qn, o);
    const float rq = rsqrtf(qn);

    float4 pp = make_float4(0.f, 0.f, 0.f, 0.f);
    float4 pm = make_float4(0.f, 0.f, 0.f, 0.f);
    float sp = 0.f, sm = 0.f;

    const float4* __restrict__ e4 = reinterpret_cast<const float4*>(e);

    int row = gw;
    // unroll-by-2 grid-stride: two independent LDG.128 in flight per warp
    for (; row + TOTW < NS; row += 2 * TOTW) {
        float4 a = e4[(size_t)row * 32 + lane];
        float4 b = e4[(size_t)(row + TOTW) * 32 + lane];

        float d0 = a.x * qf.x + a.y * qf.y + a.z * qf.z + a.w * qf.w;
        float n0 = a.x * a.x + a.y * a.y + a.z * a.z + a.w * a.w;
        float d1 = b.x * qf.x + b.y * qf.y + b.z * qf.z + b.w * qf.w;
        float n1 = b.x * b.x + b.y * b.y + b.z * b.z + b.w * b.w;
        wreduce2(d0, n0);
        wreduce2(d1, n1);

        float c0 = d0 * rsqrtf(n0) * rq;
        float c1 = d1 * rsqrtf(n1) * rq;
        float ap0 = fmaxf(c0, 0.f), am0 = fmaxf(-c0, 0.f);
        float ap1 = fmaxf(c1, 0.f), am1 = fmaxf(-c1, 0.f);
        sp += ap0 + ap1;
        sm += am0 + am1;
        pp.x += ap0 * a.x + ap1 * b.x;
        pp.y += ap0 * a.y + ap1 * b.y;
        pp.z += ap0 * a.z + ap1 * b.z;
        pp.w += ap0 * a.w + ap1 * b.w;
        pm.x += am0 * a.x + am1 * b.x;
        pm.y += am0 * a.y + am1 * b.y;
        pm.z += am0 * a.z + am1 * b.z;
        pm.w += am0 * a.w + am1 * b.w;
    }
    if (row < NS) {
        float4 a = e4[(size_t)row * 32 + lane];
        float d0 = a.x * qf.x + a.y * qf.y + a.z * qf.z + a.w * qf.w;
        float n0 = a.x * a.x + a.y * a.y + a.z * a.z + a.w * a.w;
        wreduce2(d0, n0);
        float c0 = d0 * rsqrtf(n0) * rq;
        float ap0 = fmaxf(c0, 0.f), am0 = fmaxf(-c0, 0.f);
        sp += ap0;
        sm += am0;
        pp.x += ap0 * a.x; pp.y += ap0 * a.y; pp.z += ap0 * a.z; pp.w += ap0 * a.w;
        pm.x += am0 * a.x; pm.y += am0 * a.y; pm.z += am0 * a.z; pm.w += am0 * a.w;
    }

    // Block combine (shared atomics; only 8 warps contend per address)
    __shared__ float acc[SCR_W];
    for (int i = threadIdx.x; i < SCR_W; i += NTHREADS) acc[i] = 0.f;
    __syncthreads();

    atomicAdd(&acc[lane * 4 + 0], pp.x);
    atomicAdd(&acc[lane * 4 + 1], pp.y);
    atomicAdd(&acc[lane * 4 + 2], pp.z);
    atomicAdd(&acc[lane * 4 + 3], pp.w);
    atomicAdd(&acc[H + lane * 4 + 0], pm.x);
    atomicAdd(&acc[H + lane * 4 + 1], pm.y);
    atomicAdd(&acc[H + lane * 4 + 2], pm.z);
    atomicAdd(&acc[H + lane * 4 + 3], pm.w);
    if (lane == 0) {
        atomicAdd(&acc[2 * H + 0], sp);
        atomicAdd(&acc[2 * H + 1], sm);
    }
    __syncthreads();

    for (int i = threadIdx.x; i < SCR_W; i += NTHREADS)
        g_scratch[blockIdx.x][i] = acc[i];
}

// Pass 2: single block. Reduce block partials, compute the 8 outputs.
__global__ __launch_bounds__(288) void fp_pass2(const float* __restrict__ w_key,
                                                const float* __restrict__ w_value,
                                                const float* __restrict__ mu_w,
                                                const float* __restrict__ mu_b,
                                                const float* __restrict__ sigma_w,
                                                const float* __restrict__ sigma_b,
                                                float* __restrict__ out) {
    __shared__ float tot[SCR_W];
    __shared__ float red[4][H];
    const int t = threadIdx.x;

    if (t < SCR_W) {
        float s = 0.f;
#pragma unroll 8
        for (int b = 0; b < NBLK; b++) s += g_scratch[b][t];
        tot[t] = s;
    }
    __syncthreads();

    const float Sp = fmaxf(tot[2 * H + 0], 1e-6f);
    const float Sm = fmaxf(tot[2 * H + 1], 1e-6f);

    if (t < H) {
        float hp = tot[t] / Sp;        // h vector shared by all heads with w_key > 0
        float hm = tot[H + t] / Sm;    // h vector shared by all heads with w_key < 0
        float mw = mu_w[t];
        float sw = sigma_w[t];
        red[0][t] = hp * mw;
        red[1][t] = hm * mw;
        red[2][t] = hp * sw;
        red[3][t] = hm * sw;
    }
    __syncthreads();

#pragma unroll
    for (int off = H / 2; off > 0; off >>= 1) {
        if (t < off) {
            red[0][t] += red[0][t + off];
            red[1][t] += red[1][t + off];
            red[2][t] += red[2][t + off];
            red[3][t] += red[3][t + off];
        }
        __syncthreads();
    }

    if (t < 4) {
        float wk = w_key[t];
        float wv = w_value[t];
        float dmu = (wk > 0.f) ? red[0][0] : red[1][0];
        float dsg = (wk > 0.f) ? red[2][0] : red[3][0];
        float mu_z = wv * dmu + mu_b[0];
        float x = wv * dsg + sigma_b[0];
        // softplus = max(x,0) + log1p(exp(-|x|))
        float sig_z = fmaxf(x, 0.f) + log1pf(expf(-fabsf(x)));
        out[t] = mu_z;       // mu_z[0..3]
        out[4 + t] = sig_z;  // sigma_z[0..3]
    }
}

extern "C" void kernel_launch(void* const* d_in, const int* in_sizes, int n_in,
                              void* d_out, int out_size) {
    const float* e       = (const float*)d_in[0];
    const float* w_key   = (const float*)d_in[1];
    const float* w_value = (const float*)d_in[2];
    const float* q       = (const float*)d_in[3];
    const float* mu_w    = (const float*)d_in[4];
    const float* mu_b    = (const float*)d_in[5];
    const float* sigma_w = (const float*)d_in[6];
    const float* sigma_b = (const float*)d_in[7];
    float* out = (float*)d_out;

    fp_pass1<<<NBLK, NTHREADS>>>(e, q);
    fp_pass2<<<1, 288>>>(w_key, w_value, mu_w, mu_b, sigma_w, sigma_b, out);
}

// round 2
// speedup vs baseline: 2.2955x; 2.2955x over previous
#include <cuda_runtime.h>
#include <math.h>

#define NS 100000
#define H 128
#define NBLK 512
#define NTHREADS 256
#define WPB (NTHREADS / 32)
#define TOTW (NBLK * WPB)
#define SCR_W (2 * H + 2)

// Per-block partial results, pre-dotted with mu_w/sigma_w:
// row 0: P+ . mu_w      row 1: P- . mu_w
// row 2: P+ . sigma_w   row 3: P- . sigma_w
// row 4: S+             row 5: S-
// Transposed [6][NBLK] so pass2 lanes read coalesced.
__device__ float g_part[6][NBLK];

__device__ __forceinline__ void wreduce2(float& a, float& b) {
#pragma unroll
    for (int o = 16; o > 0; o >>= 1) {
        a += __shfl_xor_sync(0xffffffffu, a, o);
        b += __shfl_xor_sync(0xffffffffu, b, o);
    }
}

// Pass 1: single sweep over e. One warp per row (32 lanes x float4 = 128 floats).
// Per row n: c_n = cos(q, e_n); accumulate S+= max(c,0), S-= max(-c,0),
// P+[h] += max(c,0) e[n,h], P-[h] += max(-c,0) e[n,h]. Then pre-dot P+/- with
// mu_w and sigma_w so only 6 scalars leave the block.
__global__ __launch_bounds__(NTHREADS) void fp_pass1(const float* __restrict__ e,
                                                     const float* __restrict__ q,
                                                     const float* __restrict__ mu_w,
                                                     const float* __restrict__ sigma_w) {
    const int lane = threadIdx.x & 31;
    const int warp = threadIdx.x >> 5;
    const int gw = blockIdx.x * WPB + warp;

    // q fragment + 1/||q||
    float4 qf = reinterpret_cast<const float4*>(q)[lane];
    float qn = qf.x * qf.x + qf.y * qf.y + qf.z * qf.z + qf.w * qf.w;
#pragma unroll
    for (int o = 16; o > 0; o >>= 1) qn += __shfl_xor_sync(0xffffffffu, qn, o);
    const float rq = rsqrtf(qn);

    float4 pp = make_float4(0.f, 0.f, 0.f, 0.f);
    float4 pm = make_float4(0.f, 0.f, 0.f, 0.f);
    float sp = 0.f, sm = 0.f;

    const float4* __restrict__ e4 = reinterpret_cast<const float4*>(e);

    int row = gw;
    for (; row + TOTW < NS; row += 2 * TOTW) {
        float4 a = e4[(size_t)row * 32 + lane];
        float4 b = e4[(size_t)(row + TOTW) * 32 + lane];

        float d0 = a.x * qf.x + a.y * qf.y + a.z * qf.z + a.w * qf.w;
        float n0 = a.x * a.x + a.y * a.y + a.z * a.z + a.w * a.w;
        float d1 = b.x * qf.x + b.y * qf.y + b.z * qf.z + b.w * qf.w;
        float n1 = b.x * b.x + b.y * b.y + b.z * b.z + b.w * b.w;
        wreduce2(d0, n0);
        wreduce2(d1, n1);

        float c0 = d0 * rsqrtf(n0) * rq;
        float c1 = d1 * rsqrtf(n1) * rq;
        float ap0 = fmaxf(c0, 0.f), am0 = fmaxf(-c0, 0.f);
        float ap1 = fmaxf(c1, 0.f), am1 = fmaxf(-c1, 0.f);
        sp += ap0 + ap1;
        sm += am0 + am1;
        pp.x += ap0 * a.x + ap1 * b.x;
        pp.y += ap0 * a.y + ap1 * b.y;
        pp.z += ap0 * a.z + ap1 * b.z;
        pp.w += ap0 * a.w + ap1 * b.w;
        pm.x += am0 * a.x + am1 * b.x;
        pm.y += am0 * a.y + am1 * b.y;
        pm.z += am0 * a.z + am1 * b.z;
        pm.w += am0 * a.w + am1 * b.w;
    }
    if (row < NS) {
        float4 a = e4[(size_t)row * 32 + lane];
        float d0 = a.x * qf.x + a.y * qf.y + a.z * qf.z + a.w * qf.w;
        float n0 = a.x * a.x + a.y * a.y + a.z * a.z + a.w * a.w;
        wreduce2(d0, n0);
        float c0 = d0 * rsqrtf(n0) * rq;
        float ap0 = fmaxf(c0, 0.f), am0 = fmaxf(-c0, 0.f);
        sp += ap0;
        sm += am0;
        pp.x += ap0 * a.x; pp.y += ap0 * a.y; pp.z += ap0 * a.z; pp.w += ap0 * a.w;
        pm.x += am0 * a.x; pm.y += am0 * a.y; pm.z += am0 * a.z; pm.w += am0 * a.w;
    }

    // Block combine of P+/P- (shared atomics, 8 warps contending) and S+/S-.
    __shared__ float acc[SCR_W];
    __shared__ float wpart[4][4];  // [quantity][warp 0..3]
    for (int i = threadIdx.x; i < SCR_W; i += NTHREADS) acc[i] = 0.f;
    __syncthreads();

    atomicAdd(&acc[lane * 4 + 0], pp.x);
    atomicAdd(&acc[lane * 4 + 1], pp.y);
    atomicAdd(&acc[lane * 4 + 2], pp.z);
    atomicAdd(&acc[lane * 4 + 3], pp.w);
    atomicAdd(&acc[H + lane * 4 + 0], pm.x);
    atomicAdd(&acc[H + lane * 4 + 1], pm.y);
    atomicAdd(&acc[H + lane * 4 + 2], pm.z);
    atomicAdd(&acc[H + lane * 4 + 3], pm.w);
    if (lane == 0) {
        atomicAdd(&acc[2 * H + 0], sp);
        atomicAdd(&acc[2 * H + 1], sm);
    }
    __syncthreads();

    // Pre-dot P+/- with mu_w and sigma_w (first 128 threads = 4 warps).
    if (threadIdx.x < H) {
        const int t = threadIdx.x;
        float hp = acc[t];
        float hm = acc[H + t];
        float mw = mu_w[t];
        float sw = sigma_w[t];
        float p0 = hp * mw, p1 = hm * mw, p2 = hp * sw, p3 = hm * sw;
#pragma unroll
        for (int o = 16; o > 0; o >>= 1) {
            p0 += __shfl_xor_sync(0xffffffffu, p0, o);
            p1 += __shfl_xor_sync(0xffffffffu, p1, o);
            p2 += __shfl_xor_sync(0xffffffffu, p2, o);
            p3 += __shfl_xor_sync(0xffffffffu, p3, o);
        }
        if (lane == 0) {
            wpart[0][warp] = p0;
            wpart[1][warp] = p1;
            wpart[2][warp] = p2;
            wpart[3][warp] = p3;
        }
    }
    __syncthreads();

    if (threadIdx.x < 4) {
        const int t = threadIdx.x;
        g_part[t][blockIdx.x] = wpart[t][0] + wpart[t][1] + wpart[t][2] + wpart[t][3];
    } else if (threadIdx.x == 4) {
        g_part[4][blockIdx.x] = acc[2 * H + 0];
    } else if (threadIdx.x == 5) {
        g_part[5][blockIdx.x] = acc[2 * H + 1];
    }
}

// Pass 2: 6 warps, one per reduced quantity; coalesced, all loads independent.
__global__ __launch_bounds__(192) void fp_pass2(const float* __restrict__ w_key,
                                                const float* __restrict__ w_value,
                                                const float* __restrict__ mu_b,
                                                const float* __restrict__ sigma_b,
                                                float* __restrict__ out) {
    __shared__ float tot[6];
    const int lane = threadIdx.x & 31;
    const int warp = threadIdx.x >> 5;

    float s = 0.f;
#pragma unroll
    for (int i = 0; i < NBLK / 32; i++) s += g_part[warp][lane + i * 32];
#pragma unroll
    for (int o = 16; o > 0; o >>= 1) s += __shfl_xor_sync(0xffffffffu, s, o);
    if (lane == 0) tot[warp] = s;
    __syncthreads();

    if (threadIdx.x < 4) {
        const int t = threadIdx.x;
        const float Sp = fmaxf(tot[4], 1e-6f);
        const float Sm = fmaxf(tot[5], 1e-6f);
        float wk = w_key[t];
        float wv = w_value[t];
        bool pos = (wk > 0.f);
        float dmu = pos ? (tot[0] / Sp) : (tot[1] / Sm);
        float dsg = pos ? (tot[2] / Sp) : (tot[3] / Sm);
        float mu_z = wv * dmu + mu_b[0];
        float x = wv * dsg + sigma_b[0];
        float sig_z = fmaxf(x, 0.f) + log1pf(expf(-fabsf(x)));
        out[t] = mu_z;
        out[4 + t] = sig_z;
    }
}

extern "C" void kernel_launch(void* const* d_in, const int* in_sizes, int n_in,
                              void* d_out, int out_size) {
    const float* e       = (const float*)d_in[0];
    const float* w_key   = (const float*)d_in[1];
    const float* w_value = (const float*)d_in[2];
    const float* q       = (const float*)d_in[3];
    const float* mu_w    = (const float*)d_in[4];
    const float* mu_b    = (const float*)d_in[5];
    const float* sigma_w = (const float*)d_in[6];
    const float* sigma_b = (const float*)d_in[7];
    float* out = (float*)d_out;

    fp_pass1<<<NBLK, NTHREADS>>>(e, q, mu_w, sigma_w);
    fp_pass2<<<1, 192>>>(w_key, w_value, mu_b, sigma_b, out);
}

// round 4
// speedup vs baseline: 3.0088x; 1.3107x over previous
#include <cuda_runtime.h>
#include <math.h>

#define NS 100000
#define NPAIR (NS / 2)
#define H 128
#define NBLK 592            // 4 * 148 SMs: one perfectly balanced wave
#define NTHREADS 256
#define WPB (NTHREADS / 32)
#define TOTW (NBLK * WPB)   // 4736 warps; each handles ~10.6 row-pairs

// Per-block partials: [quantity][block], quantities:
// 0: P+.mu_w  1: P-.mu_w  2: P+.sigma_w  3: P-.sigma_w  4: S+  5: S-
__device__ float g_part[6][NBLK];
__device__ int g_count = 0;   // last-block-done counter; reset by last block

__device__ __forceinline__ float dot8(float4 a, float4 b, float4 x, float4 y) {
    return a.x * x.x + a.y * x.y + a.z * x.z + a.w * x.w +
           b.x * y.x + b.y * y.y + b.z * y.z + b.w * y.w;
}

__global__ __launch_bounds__(NTHREADS, 4) void fp_fused_r4(
    const float* __restrict__ e, const float* __restrict__ q,
    const float* __restrict__ mu_w, const float* __restrict__ sigma_w,
    const float* __restrict__ w_key, const float* __restrict__ w_value,
    const float* __restrict__ mu_b, const float* __restrict__ sigma_b,
    float* __restrict__ out) {
    const int lane = threadIdx.x & 31;
    const int warp = threadIdx.x >> 5;
    const int sub  = lane & 15;   // lane within 16-lane row group
    const int half = lane >> 4;   // which row of the pair
    const int gw = blockIdx.x * WPB + warp;

    const float4* __restrict__ e4 = reinterpret_cast<const float4*>(e);
    const float4* __restrict__ q4 = reinterpret_cast<const float4*>(q);

    // q fragment (8 floats per lane; both halves hold the same) + 1/||q||
    float4 q0 = q4[sub * 2 + 0];
    float4 q1 = q4[sub * 2 + 1];
    float qn = dot8(q0, q1, q0, q1);
#pragma unroll
    for (int o = 8; o > 0; o >>= 1) qn += __shfl_xor_sync(0xffffffffu, qn, o);
    const float rq = rsqrtf(qn);  // identical in all lanes (16-group holds full sum)

    float pp[8] = {0, 0, 0, 0, 0, 0, 0, 0};
    float pm[8] = {0, 0, 0, 0, 0, 0, 0, 0};
    float sp = 0.f, sm = 0.f;

    int p = gw;
    for (; p + TOTW < NPAIR; p += 2 * TOTW) {
        const int i0 = (2 * p + half) * 32 + sub * 2;
        const int i1 = (2 * (p + TOTW) + half) * 32 + sub * 2;
        float4 a0 = e4[i0], a1 = e4[i0 + 1];
        float4 b0 = e4[i1], b1 = e4[i1 + 1];

        float d0 = dot8(a0, a1, q0, q1);
        float n0 = dot8(a0, a1, a0, a1);
        float d1 = dot8(b0, b1, q0, q1);
        float n1 = dot8(b0, b1, b0, b1);
#pragma unroll
        for (int o = 8; o > 0; o >>= 1) {
            d0 += __shfl_xor_sync(0xffffffffu, d0, o);
            n0 += __shfl_xor_sync(0xffffffffu, n0, o);
            d1 += __shfl_xor_sync(0xffffffffu, d1, o);
            n1 += __shfl_xor_sync(0xffffffffu, n1, o);
        }
        float r0 = rsqrtf(n0) * rq;
        float r1 = rsqrtf(n1) * rq;
        float ap0 = fmaxf(d0, 0.f) * r0, am0 = fmaxf(-d0, 0.f) * r0;
        float ap1 = fmaxf(d1, 0.f) * r1, am1 = fmaxf(-d1, 0.f) * r1;
        sp += ap0 + ap1;
        sm += am0 + am1;
        pp[0] += ap0 * a0.x + ap1 * b0.x;  pm[0] += am0 * a0.x + am1 * b0.x;
        pp[1] += ap0 * a0.y + ap1 * b0.y;  pm[1] += am0 * a0.y + am1 * b0.y;
        pp[2] += ap0 * a0.z + ap1 * b0.z;  pm[2] += am0 * a0.z + am1 * b0.z;
        pp[3] += ap0 * a0.w + ap1 * b0.w;  pm[3] += am0 * a0.w + am1 * b0.w;
        pp[4] += ap0 * a1.x + ap1 * b1.x;  pm[4] += am0 * a1.x + am1 * b1.x;
        pp[5] += ap0 * a1.y + ap1 * b1.y;  pm[5] += am0 * a1.y + am1 * b1.y;
        pp[6] += ap0 * a1.z + ap1 * b1.z;  pm[6] += am0 * a1.z + am1 * b1.z;
        pp[7] += ap0 * a1.w + ap1 * b1.w;  pm[7] += am0 * a1.w + am1 * b1.w;
    }
    if (p < NPAIR) {
        const int i0 = (2 * p + half) * 32 + sub * 2;
        float4 a0 = e4[i0], a1 = e4[i0 + 1];
        float d0 = dot8(a0, a1, q0, q1);
        float n0 = dot8(a0, a1, a0, a1);
#pragma unroll
        for (int o = 8; o > 0; o >>= 1) {
            d0 += __shfl_xor_sync(0xffffffffu, d0, o);
            n0 += __shfl_xor_sync(0xffffffffu, n0, o);
        }
        float r0 = rsqrtf(n0) * rq;
        float ap0 = fmaxf(d0, 0.f) * r0, am0 = fmaxf(-d0, 0.f) * r0;
        sp += ap0;
        sm += am0;
        pp[0] += ap0 * a0.x;  pm[0] += am0 * a0.x;
        pp[1] += ap0 * a0.y;  pm[1] += am0 * a0.y;
        pp[2] += ap0 * a0.z;  pm[2] += am0 * a0.z;
        pp[3] += ap0 * a0.w;  pm[3] += am0 * a0.w;
        pp[4] += ap0 * a1.x;  pm[4] += am0 * a1.x;
        pp[5] += ap0 * a1.y;  pm[5] += am0 * a1.y;
        pp[6] += ap0 * a1.z;  pm[6] += am0 * a1.z;
        pp[7] += ap0 * a1.w;  pm[7] += am0 * a1.w;
    }

    // ── Warp epilogue: combine halves, pre-dot with mu_w/sigma_w ──
#pragma unroll
    for (int i = 0; i < 8; i++) {
        pp[i] += __shfl_xor_sync(0xffffffffu, pp[i], 16);
        pm[i] += __shfl_xor_sync(0xffffffffu, pm[i], 16);
    }
    const float4* __restrict__ mw4 = reinterpret_cast<const float4*>(mu_w);
    const float4* __restrict__ sw4 = reinterpret_cast<const float4*>(sigma_w);
    float4 m0 = mw4[sub * 2], m1 = mw4[sub * 2 + 1];
    float4 s0 = sw4[sub * 2], s1 = sw4[sub * 2 + 1];
    float mwv[8] = {m0.x, m0.y, m0.z, m0.w, m1.x, m1.y, m1.z, m1.w};
    float swv[8] = {s0.x, s0.y, s0.z, s0.w, s1.x, s1.y, s1.z, s1.w};
    float t0 = 0, t1 = 0, t2 = 0, t3 = 0;
#pragma unroll
    for (int i = 0; i < 8; i++) {
        t0 += pp[i] * mwv[i];
        t1 += pm[i] * mwv[i];
        t2 += pp[i] * swv[i];
        t3 += pm[i] * swv[i];
    }
    // reduce over the 16 column groups (both halves hold identical pp/pm now)
#pragma unroll
    for (int o = 8; o > 0; o >>= 1) {
        t0 += __shfl_xor_sync(0xffffffffu, t0, o);
        t1 += __shfl_xor_sync(0xffffffffu, t1, o);
        t2 += __shfl_xor_sync(0xffffffffu, t2, o);
        t3 += __shfl_xor_sync(0xffffffffu, t3, o);
    }
    // sp/sm held 16x per row (one copy per lane of the 16-group) -> scale 1/16
#pragma unroll
    for (int o = 16; o > 0; o >>= 1) {
        sp += __shfl_xor_sync(0xffffffffu, sp, o);
        sm += __shfl_xor_sync(0xffffffffu, sm, o);
    }

    __shared__ float wsum[WPB][6];
    __shared__ int is_last;
    if (lane == 0) {
        wsum[warp][0] = t0;
        wsum[warp][1] = t1;
        wsum[warp][2] = t2;
        wsum[warp][3] = t3;
        wsum[warp][4] = sp * 0.0625f;
        wsum[warp][5] = sm * 0.0625f;
    }
    __syncthreads();
    if (threadIdx.x < 6) {
        float s = 0.f;
#pragma unroll
        for (int w = 0; w < WPB; w++) s += wsum[w][threadIdx.x];
        g_part[threadIdx.x][blockIdx.x] = s;
    }
    __threadfence();
    __syncthreads();
    if (threadIdx.x == 0)
        is_last = (atomicAdd(&g_count, 1) == NBLK - 1) ? 1 : 0;
    __syncthreads();
    if (!is_last) return;

    // ── Last block: final reduce + the 8 outputs ──
    __shared__ float tot[6];
    if (warp < 6) {
        float s = 0.f;
#pragma unroll
        for (int i = 0; i < (NBLK + 31) / 32; i++) {
            int j = lane + i * 32;
            if (j < NBLK) s += __ldcg(&g_part[warp][j]);
        }
#pragma unroll
        for (int o = 16; o > 0; o >>= 1) s += __shfl_xor_sync(0xffffffffu, s, o);
        if (lane == 0) tot[warp] = s;
    }
    __syncthreads();
    if (threadIdx.x < 4) {
        const int t = threadIdx.x;
        const float Sp = fmaxf(tot[4], 1e-6f);
        const float Sm = fmaxf(tot[5], 1e-6f);
        float wk = w_key[t];
        float wv = w_value[t];
        bool pos = (wk > 0.f);
        float dmu = pos ? (tot[0] / Sp) : (tot[1] / Sm);
        float dsg = pos ? (tot[2] / Sp) : (tot[3] / Sm);
        float mu_z = wv * dmu + mu_b[0];
        float x = wv * dsg + sigma_b[0];
        float sig_z = fmaxf(x, 0.f) + log1pf(expf(-fabsf(x)));
        out[t] = mu_z;
        out[4 + t] = sig_z;
    }
    if (threadIdx.x == 0) g_count = 0;  // reset for next graph replay
}

extern "C" void kernel_launch(void* const* d_in, const int* in_sizes, int n_in,
                              void* d_out, int out_size) {
    const float* e       = (const float*)d_in[0];
    const float* w_key   = (const float*)d_in[1];
    const float* w_value = (const float*)d_in[2];
    const float* q       = (const float*)d_in[3];
    const float* mu_w    = (const float*)d_in[4];
    const float* mu_b    = (const float*)d_in[5];
    const float* sigma_w = (const float*)d_in[6];
    const float* sigma_b = (const float*)d_in[7];
    float* out = (float*)d_out;

    fp_fused_r4<<<NBLK, NTHREADS>>>(e, q, mu_w, sigma_w, w_key, w_value, mu_b, sigma_b, out);
}

// round 5
// speedup vs baseline: 3.0488x; 1.0133x over previous
#include <cuda_runtime.h>
#include <math.h>

#define NS 100000
#define NPAIR (NS / 2)
#define H 128
#define NBLK 444            // 3 blocks/SM * 148 SMs: one balanced wave at occ=3
#define NTHREADS 256
#define WPB (NTHREADS / 32)
#define TOTW (NBLK * WPB)   // 3552 warps

// Per-block partials: [quantity][block]:
// 0: P+.mu_w  1: P-.mu_w  2: P+.sigma_w  3: P-.sigma_w  4: S+  5: S-
__device__ float g_part[6][NBLK];
__device__ int g_count = 0;   // last-block-done counter; reset by last block

__device__ __forceinline__ float dot8(float4 a, float4 b, float4 x, float4 y) {
    return a.x * x.x + a.y * x.y + a.z * x.z + a.w * x.w +
           b.x * y.x + b.y * y.y + b.z * y.z + b.w * y.w;
}

__global__ __launch_bounds__(NTHREADS, 3) void fp_fused_r5(
    const float* __restrict__ e, const float* __restrict__ q,
    const float* __restrict__ mu_w, const float* __restrict__ sigma_w,
    const float* __restrict__ w_key, const float* __restrict__ w_value,
    const float* __restrict__ mu_b, const float* __restrict__ sigma_b,
    float* __restrict__ out) {
    const int lane = threadIdx.x & 31;
    const int warp = threadIdx.x >> 5;
    const int sub  = lane & 15;   // lane within 16-lane row group
    const int half = lane >> 4;   // which row of the pair
    const int gw = blockIdx.x * WPB + warp;

    const float4* __restrict__ e4 = reinterpret_cast<const float4*>(e);
    const float4* __restrict__ q4 = reinterpret_cast<const float4*>(q);

    float4 q0 = q4[sub * 2 + 0];
    float4 q1 = q4[sub * 2 + 1];
    float qn = dot8(q0, q1, q0, q1);
#pragma unroll
    for (int o = 8; o > 0; o >>= 1) qn += __shfl_xor_sync(0xffffffffu, qn, o);
    const float rq = rsqrtf(qn);

    float pp[8] = {0, 0, 0, 0, 0, 0, 0, 0};
    float pm[8] = {0, 0, 0, 0, 0, 0, 0, 0};
    float sp = 0.f, sm = 0.f;

    int p = gw;
    // Main loop: 4 pairs (8 rows) per iteration — 8 LDG.128 in flight,
    // 8 independent shuffle chains.
    for (; p + 3 * TOTW < NPAIR; p += 4 * TOTW) {
        float4 A[4][2];
        float d[4], n[4];
#pragma unroll
        for (int k = 0; k < 4; k++) {
            const int i0 = (2 * (p + k * TOTW) + half) * 32 + sub * 2;
            A[k][0] = e4[i0];
            A[k][1] = e4[i0 + 1];
        }
#pragma unroll
        for (int k = 0; k < 4; k++) {
            d[k] = dot8(A[k][0], A[k][1], q0, q1);
            n[k] = dot8(A[k][0], A[k][1], A[k][0], A[k][1]);
        }
#pragma unroll
        for (int o = 8; o > 0; o >>= 1) {
#pragma unroll
            for (int k = 0; k < 4; k++) {
                d[k] += __shfl_xor_sync(0xffffffffu, d[k], o);
                n[k] += __shfl_xor_sync(0xffffffffu, n[k], o);
            }
        }
        float ap[4], am[4];
#pragma unroll
        for (int k = 0; k < 4; k++) {
            float r = rsqrtf(n[k]) * rq;
            ap[k] = fmaxf(d[k], 0.f) * r;
            am[k] = fmaxf(-d[k], 0.f) * r;
            sp += ap[k];
            sm += am[k];
        }
#pragma unroll
        for (int k = 0; k < 4; k++) {
            pp[0] += ap[k] * A[k][0].x;  pm[0] += am[k] * A[k][0].x;
            pp[1] += ap[k] * A[k][0].y;  pm[1] += am[k] * A[k][0].y;
            pp[2] += ap[k] * A[k][0].z;  pm[2] += am[k] * A[k][0].z;
            pp[3] += ap[k] * A[k][0].w;  pm[3] += am[k] * A[k][0].w;
            pp[4] += ap[k] * A[k][1].x;  pm[4] += am[k] * A[k][1].x;
            pp[5] += ap[k] * A[k][1].y;  pm[5] += am[k] * A[k][1].y;
            pp[6] += ap[k] * A[k][1].z;  pm[6] += am[k] * A[k][1].z;
            pp[7] += ap[k] * A[k][1].w;  pm[7] += am[k] * A[k][1].w;
        }
    }
    // Tail: single pair at a time.
    for (; p < NPAIR; p += TOTW) {
        const int i0 = (2 * p + half) * 32 + sub * 2;
        float4 a0 = e4[i0], a1 = e4[i0 + 1];
        float d0 = dot8(a0, a1, q0, q1);
        float n0 = dot8(a0, a1, a0, a1);
#pragma unroll
        for (int o = 8; o > 0; o >>= 1) {
            d0 += __shfl_xor_sync(0xffffffffu, d0, o);
            n0 += __shfl_xor_sync(0xffffffffu, n0, o);
        }
        float r0 = rsqrtf(n0) * rq;
        float ap0 = fmaxf(d0, 0.f) * r0, am0 = fmaxf(-d0, 0.f) * r0;
        sp += ap0;
        sm += am0;
        pp[0] += ap0 * a0.x;  pm[0] += am0 * a0.x;
        pp[1] += ap0 * a0.y;  pm[1] += am0 * a0.y;
        pp[2] += ap0 * a0.z;  pm[2] += am0 * a0.z;
        pp[3] += ap0 * a0.w;  pm[3] += am0 * a0.w;
        pp[4] += ap0 * a1.x;  pm[4] += am0 * a1.x;
        pp[5] += ap0 * a1.y;  pm[5] += am0 * a1.y;
        pp[6] += ap0 * a1.z;  pm[6] += am0 * a1.z;
        pp[7] += ap0 * a1.w;  pm[7] += am0 * a1.w;
    }

    // ── Warp epilogue: combine halves, pre-dot with mu_w/sigma_w ──
#pragma unroll
    for (int i = 0; i < 8; i++) {
        pp[i] += __shfl_xor_sync(0xffffffffu, pp[i], 16);
        pm[i] += __shfl_xor_sync(0xffffffffu, pm[i], 16);
    }
    const float4* __restrict__ mw4 = reinterpret_cast<const float4*>(mu_w);
    const float4* __restrict__ sw4 = reinterpret_cast<const float4*>(sigma_w);
    float4 m0 = mw4[sub * 2], m1 = mw4[sub * 2 + 1];
    float4 s0 = sw4[sub * 2], s1 = sw4[sub * 2 + 1];
    float mwv[8] = {m0.x, m0.y, m0.z, m0.w, m1.x, m1.y, m1.z, m1.w};
    float swv[8] = {s0.x, s0.y, s0.z, s0.w, s1.x, s1.y, s1.z, s1.w};
    float t0 = 0, t1 = 0, t2 = 0, t3 = 0;
#pragma unroll
    for (int i = 0; i < 8; i++) {
        t0 += pp[i] * mwv[i];
        t1 += pm[i] * mwv[i];
        t2 += pp[i] * swv[i];
        t3 += pm[i] * swv[i];
    }
#pragma unroll
    for (int o = 8; o > 0; o >>= 1) {
        t0 += __shfl_xor_sync(0xffffffffu, t0, o);
        t1 += __shfl_xor_sync(0xffffffffu, t1, o);
        t2 += __shfl_xor_sync(0xffffffffu, t2, o);
        t3 += __shfl_xor_sync(0xffffffffu, t3, o);
    }
    // sp/sm held 16x per row (one copy per lane of the 16-group) -> scale 1/16
#pragma unroll
    for (int o = 16; o > 0; o >>= 1) {
        sp += __shfl_xor_sync(0xffffffffu, sp, o);
        sm += __shfl_xor_sync(0xffffffffu, sm, o);
    }

    __shared__ float wsum[WPB][6];
    __shared__ int is_last;
    if (lane == 0) {
        wsum[warp][0] = t0;
        wsum[warp][1] = t1;
        wsum[warp][2] = t2;
        wsum[warp][3] = t3;
        wsum[warp][4] = sp * 0.0625f;
        wsum[warp][5] = sm * 0.0625f;
    }
    __syncthreads();
    if (threadIdx.x < 6) {
        float s = 0.f;
#pragma unroll
        for (int w = 0; w < WPB; w++) s += wsum[w][threadIdx.x];
        g_part[threadIdx.x][blockIdx.x] = s;
    }
    __threadfence();
    __syncthreads();
    if (threadIdx.x == 0)
        is_last = (atomicAdd(&g_count, 1) == NBLK - 1) ? 1 : 0;
    __syncthreads();
    if (!is_last) return;

    // ── Last block: final reduce + the 8 outputs ──
    __shared__ float tot[6];
    if (warp < 6) {
        float s = 0.f;
#pragma unroll
        for (int i = 0; i < (NBLK + 31) / 32; i++) {
            int j = lane + i * 32;
            if (j < NBLK) s += __ldcg(&g_part[warp][j]);
        }
#pragma unroll
        for (int o = 16; o > 0; o >>= 1) s += __shfl_xor_sync(0xffffffffu, s, o);
        if (lane == 0) tot[warp] = s;
    }
    __syncthreads();
    if (threadIdx.x < 4) {
        const int t = threadIdx.x;
        const float Sp = fmaxf(tot[4], 1e-6f);
        const float Sm = fmaxf(tot[5], 1e-6f);
        float wk = w_key[t];
        float wv = w_value[t];
        bool pos = (wk > 0.f);
        float dmu = pos ? (tot[0] / Sp) : (tot[1] / Sm);
        float dsg = pos ? (tot[2] / Sp) : (tot[3] / Sm);
        float mu_z = wv * dmu + mu_b[0];
        float x = wv * dsg + sigma_b[0];
        float sig_z = fmaxf(x, 0.f) + log1pf(expf(-fabsf(x)));
        out[t] = mu_z;
        out[4 + t] = sig_z;
    }
    if (threadIdx.x == 0) g_count = 0;  // reset for next graph replay
}

extern "C" void kernel_launch(void* const* d_in, const int* in_sizes, int n_in,
                              void* d_out, int out_size) {
    const float* e       = (const float*)d_in[0];
    const float* w_key   = (const float*)d_in[1];
    const float* w_value = (const float*)d_in[2];
    const float* q       = (const float*)d_in[3];
    const float* mu_w    = (const float*)d_in[4];
    const float* mu_b    = (const float*)d_in[5];
    const float* sigma_w = (const float*)d_in[6];
    const float* sigma_b = (const float*)d_in[7];
    float* out = (float*)d_out;

    fp_fused_r5<<<NBLK, NTHREADS>>>(e, q, mu_w, sigma_w, w_key, w_value, mu_b, sigma_b, out);
}